// round 14
// baseline (speedup 1.0000x reference)
#include <cuda_runtime.h>
#include <cuda_bf16.h>
#include <math.h>
#include <stdint.h>

#define BB 256
#define TT 512
#define HH 1024
#define OO 256

#define CK 64                   // K per chunk PER HALF
#define NCHUNK 8                // 8 x 64 x 2 halves = 1024
#define STAGE_B 49152
#define STAGES 2
#define SMEM_TOTAL (STAGES * STAGE_B + 512)   // 98816 -> 2 CTAs/SM

// offsets inside a stage (h = K-half)
#define AH_OFF(h) ((h) * 4096)
#define AL_OFF(h) (8192 + (h) * 4096)
#define BH_OFF(h) (16384 + (h) * 8192)
#define BL_OFF(h) (32768 + (h) * 8192)

__device__ __align__(1024) __nv_bfloat16 g_h_hi[2][BB * HH];
__device__ __align__(1024) __nv_bfloat16 g_h_lo[2][BB * HH];
__device__ __align__(1024) __nv_bfloat16 g_Wt_hi[HH * HH];
__device__ __align__(1024) __nv_bfloat16 g_Wt_lo[HH * HH];

// ---------- PTX helpers (sm_90-generic only) ----------
__device__ __forceinline__ uint32_t smem_u32(const void* p) {
    uint32_t a;
    asm("{ .reg .u64 t; cvta.to.shared.u64 t, %1; cvt.u32.u64 %0, t; }" : "=r"(a) : "l"(p));
    return a;
}
__device__ __forceinline__ void cp16(uint32_t d, const void* s) {
    asm volatile("cp.async.cg.shared.global [%0], [%1], 16;" :: "r"(d), "l"(s) : "memory");
}
#define CP_COMMIT() asm volatile("cp.async.commit_group;" ::: "memory")
#define CP_WAIT1()  asm volatile("cp.async.wait_group 1;" ::: "memory")
#define GRIDDEP_WAIT()   asm volatile("griddepcontrol.wait;" ::: "memory")
#define GRIDDEP_LAUNCH() asm volatile("griddepcontrol.launch_dependents;" ::: "memory")

__device__ __forceinline__ void ldsm4(uint32_t* r, uint32_t a) {
    asm volatile("ldmatrix.sync.aligned.m8n8.x4.shared.b16 {%0,%1,%2,%3}, [%4];"
                 : "=r"(r[0]), "=r"(r[1]), "=r"(r[2]), "=r"(r[3]) : "r"(a));
}
__device__ __forceinline__ void mma16816(float* c, const uint32_t* a,
                                         uint32_t b0, uint32_t b1) {
    asm volatile(
        "mma.sync.aligned.m16n8k16.row.col.f32.bf16.bf16.f32 "
        "{%0,%1,%2,%3},{%4,%5,%6,%7},{%8,%9},{%0,%1,%2,%3};"
        : "+f"(c[0]), "+f"(c[1]), "+f"(c[2]), "+f"(c[3])
        : "r"(a[0]), "r"(a[1]), "r"(a[2]), "r"(a[3]), "r"(b0), "r"(b1));
}

// Fast tanh: 1 - 2/(e^{2y}+1). Saturates to +/-1; err ~1e-6.
__device__ __forceinline__ float ftanh(float y) {
    float e = __expf(2.f * y);
    return 1.f - __fdividef(2.f, e + 1.f);
}

// ---------- setup kernels ----------

__global__ __launch_bounds__(256) void wsplit_kernel(const float* __restrict__ W_ih) {
    __shared__ float tile[32][33];
    const int k0 = blockIdx.x * 32;
    const int j0 = blockIdx.y * 32;
    const int tx = threadIdx.x & 31;
    const int ty = threadIdx.x >> 5;
    #pragma unroll
    for (int i = 0; i < 4; ++i) {
        int k = ty + i * 8;
        tile[k][tx] = W_ih[(size_t)(1 + k0 + k) * HH + j0 + tx];
    }
    __syncthreads();
    #pragma unroll
    for (int i = 0; i < 4; ++i) {
        int j = ty + i * 8;
        float v = tile[tx][j];
        __nv_bfloat16 hi = __float2bfloat16(v);
        float lo = v - __bfloat162float(hi);
        g_Wt_hi[(size_t)(j0 + j) * HH + k0 + tx] = hi;
        g_Wt_lo[(size_t)(j0 + j) * HH + k0 + tx] = __float2bfloat16(lo);
    }
}

__global__ __launch_bounds__(256) void step0_kernel(
    const float* __restrict__ x, const float* __restrict__ W_ih,
    const float* __restrict__ b_ih) {
    int j = (blockIdx.x & 3) * 256 + threadIdx.x;
    int b = blockIdx.x >> 2;
    float v = tanhf(x[b * TT] * W_ih[j] + b_ih[j]);
    __nv_bfloat16 hi = __float2bfloat16(v);
    g_h_hi[1][b * HH + j] = hi;
    g_h_lo[1][b * HH + j] = __float2bfloat16(v - __bfloat162float(hi));
}

// One step. CTA 32(b) x 64(j), 256 threads, 8 warps; warp tile 32x16
// (warp_n = wid&3, kh = wid>>2). CK=64 chunks, 2 stages, depth-1 pipe.
// 2 CTAs/SM: the NEXT step's CTA co-resides during this CTA's tail (PDL).
__global__ __launch_bounds__(256, 2) void mma_step(
    const float* __restrict__ x,
    const float* __restrict__ W_ih,
    const float* __restrict__ b_ih,
    int t, int rd) {
    extern __shared__ __align__(1024) char smem[];
    const uint32_t sb = smem_u32(smem);
    float* wx_s = (float*)(smem + STAGES * STAGE_B);
    float* bi_s = wx_s + 64;

    const int tid = threadIdx.x;
    const int wid = tid >> 5;
    const int lane = tid & 31;
    const int j0 = blockIdx.x * 64;
    const int m0 = blockIdx.y * 32;

    if (tid < 64) {
        wx_s[tid] = W_ih[j0 + tid];
        bi_s[tid] = b_ih[j0 + tid];
    }

    // ---- cp.async roles ----
    const int row8 = tid >> 3;          // 0..31
    const int colq = tid & 7;           // 16B column
    const uint32_t xcol = (uint32_t)(colq ^ (row8 & 7));
    const size_t a_src = (size_t)(m0 + row8) * HH + colq * 8;
    const __nv_bfloat16* wbh = g_Wt_hi + (size_t)(j0 + row8) * HH + colq * 8;
    const __nv_bfloat16* wbl = g_Wt_lo + (size_t)(j0 + row8) * HH + colq * 8;
    const uint32_t a_dst  = (uint32_t)row8 * 128 + xcol * 16;
    const uint32_t b_dst1 = a_dst + 32 * 128;

#define ISSUE_B(cc, stg) do {                                            \
    const uint32_t st_ = sb + (uint32_t)(stg) * STAGE_B;                 \
    const int k0_ = (cc) * CK;                                           \
    cp16(st_ + BH_OFF(0) + a_dst,  wbh + k0_);                           \
    cp16(st_ + BH_OFF(0) + b_dst1, wbh + 32 * HH + k0_);                 \
    cp16(st_ + BH_OFF(1) + a_dst,  wbh + 512 + k0_);                     \
    cp16(st_ + BH_OFF(1) + b_dst1, wbh + 32 * HH + 512 + k0_);           \
    cp16(st_ + BL_OFF(0) + a_dst,  wbl + k0_);                           \
    cp16(st_ + BL_OFF(0) + b_dst1, wbl + 32 * HH + k0_);                 \
    cp16(st_ + BL_OFF(1) + a_dst,  wbl + 512 + k0_);                     \
    cp16(st_ + BL_OFF(1) + b_dst1, wbl + 32 * HH + 512 + k0_);           \
} while (0)

#define ISSUE_A(cc, stg) do {                                            \
    const uint32_t st_ = sb + (uint32_t)(stg) * STAGE_B;                 \
    const int k0_ = (cc) * CK;                                           \
    cp16(st_ + AH_OFF(0) + a_dst,  hhi + a_src + k0_);                   \
    cp16(st_ + AH_OFF(1) + a_dst,  hhi + a_src + 512 + k0_);             \
    cp16(st_ + AL_OFF(0) + a_dst,  hlo + a_src + k0_);                   \
    cp16(st_ + AL_OFF(1) + a_dst,  hlo + a_src + 512 + k0_);             \
} while (0)

    // ---- compute roles ----
    const int kh = wid >> 2;
    const int warp_n = wid & 3;
    const int lrow = lane & 7;
    const uint32_t arow0 = (uint32_t)(lrow + ((lane >> 3) & 1) * 8) * 128;
    const uint32_t arow1 = arow0 + 16 * 128;
    const uint32_t brow  = (uint32_t)(warp_n * 16 + lrow + (lane >> 4) * 8) * 128;
    const int acsel = lane >> 4;
    const int bcsel = (lane >> 3) & 1;
    const uint32_t ahb = AH_OFF(kh), alb = AL_OFF(kh);
    const uint32_t bhb = BH_OFF(kh), blb = BL_OFF(kh);

#define LOAD_A(stb_, kk_) do {                                           \
    const uint32_t cA = (uint32_t)((2 * (kk_) + acsel) ^ lrow) * 16;     \
    ldsm4(&ah[0][0], (stb_) + ahb + arow0 + cA);                         \
    ldsm4(&ah[1][0], (stb_) + ahb + arow1 + cA);                         \
    ldsm4(&al[0][0], (stb_) + alb + arow0 + cA);                         \
    ldsm4(&al[1][0], (stb_) + alb + arow1 + cA);                         \
} while (0)

#define LOAD_B(i_, stb_, kk_) do {                                       \
    const uint32_t cB = (uint32_t)((2 * (kk_) + bcsel) ^ lrow) * 16;     \
    ldsm4(bh[i_], (stb_) + bhb + brow + cB);                             \
    ldsm4(bl[i_], (stb_) + blb + brow + cB);                             \
} while (0)

    // x prefetch: the 2 rows this warp finalizes (m-block = kh)
    const int er0 = m0 + kh * 16 + (lane >> 2);
    float xv0 = x[er0 * TT + t];
    float xv1 = x[(er0 + 8) * TT + t];

    // ---- PDL prologue: W chunks 0,1 pre-wait, then h chunks 0,1 ----
    ISSUE_B(0, 0); CP_COMMIT();
    ISSUE_B(1, 1); CP_COMMIT();

    GRIDDEP_WAIT();   // previous step's h now visible

    const __nv_bfloat16* __restrict__ hhi = g_h_hi[rd];
    const __nv_bfloat16* __restrict__ hlo = g_h_lo[rd];
    ISSUE_A(0, 0); CP_COMMIT();
    ISSUE_A(1, 1); CP_COMMIT();

    float acc[2][3][2][4];
    #pragma unroll
    for (int m = 0; m < 2; ++m)
        #pragma unroll
        for (int p = 0; p < 3; ++p)
            #pragma unroll
            for (int n = 0; n < 2; ++n)
                #pragma unroll
                for (int i = 0; i < 4; ++i) acc[m][p][n][i] = 0.f;

    // Groups: B0,B1,A0,A1, then one combined group per loop iter.
    // iter c: wait_group 1 guarantees chunk c complete (see accounting);
    // compute c; sync; issue chunk c+2 into stage c&1 (just freed).
    #pragma unroll 1
    for (int c = 0; c < NCHUNK; ++c) {
        CP_WAIT1();
        __syncthreads();

        const uint32_t stb = sb + (uint32_t)(c & 1) * STAGE_B;
        uint32_t ah[2][4], al[2][4], bh[2][4], bl[2][4];
        LOAD_B(0, stb, 0);
        #pragma unroll
        for (int kk = 0; kk < CK / 16; ++kk) {
            const int cur = kk & 1;
            LOAD_A(stb, kk);
            if (kk < CK / 16 - 1) LOAD_B(cur ^ 1, stb, kk + 1);
            #pragma unroll
            for (int m = 0; m < 2; ++m) {
                mma16816(acc[m][0][0], ah[m], bh[cur][0], bh[cur][1]);
                mma16816(acc[m][0][1], ah[m], bh[cur][2], bh[cur][3]);
                mma16816(acc[m][1][0], ah[m], bl[cur][0], bl[cur][1]);
                mma16816(acc[m][1][1], ah[m], bl[cur][2], bl[cur][3]);
                mma16816(acc[m][2][0], al[m], bh[cur][0], bh[cur][1]);
                mma16816(acc[m][2][1], al[m], bh[cur][2], bh[cur][3]);
            }
        }

        __syncthreads();   // all warps done reading stage c&1
        if (c + 2 < NCHUNK) {
            ISSUE_B(c + 2, c & 1);
            ISSUE_A(c + 2, c & 1);
        }
        CP_COMMIT();       // always commit (empty groups keep accounting uniform)
    }

    GRIDDEP_LAUNCH();  // next step may launch; its CTA can co-reside NOW

    float s[2][2][4];
    #pragma unroll
    for (int m = 0; m < 2; ++m)
        #pragma unroll
        for (int n = 0; n < 2; ++n)
            #pragma unroll
            for (int i = 0; i < 4; ++i)
                s[m][n][i] = acc[m][0][n][i] + acc[m][1][n][i] + acc[m][2][n][i];

    // ---- symmetric cross-half exchange: warp finalizes m-block == kh ----
    float* scratch = (float*)smem;   // stage 0, free after last sync above
    const uint32_t slot = (uint32_t)(warp_n * 32 + lane) * 8;
    const int om = kh ^ 1;
    {
        float4* p = (float4*)(scratch + (uint32_t)kh * 1024 + slot);
        p[0] = make_float4(s[om][0][0], s[om][0][1], s[om][0][2], s[om][0][3]);
        p[1] = make_float4(s[om][1][0], s[om][1][1], s[om][1][2], s[om][1][3]);
    }
    __syncthreads();
    {
        const float4* q = (const float4*)(scratch + (uint32_t)om * 1024 + slot);
        float4 q0 = q[0], q1 = q[1];
        s[kh][0][0] += q0.x; s[kh][0][1] += q0.y; s[kh][0][2] += q0.z; s[kh][0][3] += q0.w;
        s[kh][1][0] += q1.x; s[kh][1][1] += q1.y; s[kh][1][2] += q1.z; s[kh][1][3] += q1.w;
    }

    // ---- epilogue: every warp writes its own 16-row m-block ----
    {
        __nv_bfloat16* ph = g_h_hi[rd ^ 1];
        __nv_bfloat16* pl = g_h_lo[rd ^ 1];
        const int r0 = er0;
        const int r1 = r0 + 8;
        #pragma unroll
        for (int n = 0; n < 2; ++n) {
            const int cj = warp_n * 16 + n * 8 + (lane & 3) * 2;
            const float wxa = wx_s[cj], wxb = wx_s[cj + 1];
            const float bia = bi_s[cj], bib = bi_s[cj + 1];
            float v00 = ftanh(s[kh][n][0] + xv0 * wxa + bia);
            float v01 = ftanh(s[kh][n][1] + xv0 * wxb + bib);
            float v10 = ftanh(s[kh][n][2] + xv1 * wxa + bia);
            float v11 = ftanh(s[kh][n][3] + xv1 * wxb + bib);

            __nv_bfloat162 h0, l0, h1, l1;
            h0.x = __float2bfloat16(v00); h0.y = __float2bfloat16(v01);
            l0.x = __float2bfloat16(v00 - __bfloat162float(h0.x));
            l0.y = __float2bfloat16(v01 - __bfloat162float(h0.y));
            h1.x = __float2bfloat16(v10); h1.y = __float2bfloat16(v11);
            l1.x = __float2bfloat16(v10 - __bfloat162float(h1.x));
            l1.y = __float2bfloat16(v11 - __bfloat162float(h1.y));

            const size_t o0 = (size_t)r0 * HH + j0 + cj;
            const size_t o1 = (size_t)r1 * HH + j0 + cj;
            *(uint32_t*)(ph + o0) = *(uint32_t*)&h0;
            *(uint32_t*)(pl + o0) = *(uint32_t*)&l0;
            *(uint32_t*)(ph + o1) = *(uint32_t*)&h1;
            *(uint32_t*)(pl + o1) = *(uint32_t*)&l1;
        }
    }
#undef ISSUE_B
#undef ISSUE_A
#undef LOAD_A
#undef LOAD_B
}

// out = h_final @ W_ho + b_ho ; h_final = hi+lo in buffer 0
__global__ __launch_bounds__(256) void out_kernel(
    const float* __restrict__ W_ho, const float* __restrict__ b_ho,
    float* __restrict__ out) {
    __shared__ __align__(16) float hsm[2 * HH];
    const int b0 = blockIdx.x * 2;
    const __nv_bfloat16* sh = &g_h_hi[0][(size_t)b0 * HH];
    const __nv_bfloat16* sl = &g_h_lo[0][(size_t)b0 * HH];
    for (int i = threadIdx.x; i < 2 * HH; i += 256)
        hsm[i] = __bfloat162float(sh[i]) + __bfloat162float(sl[i]);
    __syncthreads();

    const int o = threadIdx.x;
    float a0 = 0.f, a1 = 0.f;
    #pragma unroll 16
    for (int k = 0; k < HH; ++k) {
        float w = W_ho[k * OO + o];
        a0 += hsm[k] * w;
        a1 += hsm[HH + k] * w;
    }
    out[b0 * OO + o]       = a0 + b_ho[o];
    out[(b0 + 1) * OO + o] = a1 + b_ho[o];
}

extern "C" void kernel_launch(void* const* d_in, const int* in_sizes, int n_in,
                              void* d_out, int out_size) {
    const float* x    = (const float*)d_in[0];
    const float* W_ih = (const float*)d_in[1];
    const float* b_ih = (const float*)d_in[2];
    const float* W_ho = (const float*)d_in[3];
    const float* b_ho = (const float*)d_in[4];
    float* out = (float*)d_out;

    static int once = 0;
    if (!once) {
        cudaFuncSetAttribute(mma_step, cudaFuncAttributeMaxDynamicSharedMemorySize,
                             SMEM_TOTAL);
        once = 1;
    }

    wsplit_kernel<<<dim3(32, 32), 256>>>(W_ih);
    step0_kernel<<<BB * 4, 256>>>(x, W_ih, b_ih);

    cudaLaunchAttribute attr[1];
    attr[0].id = cudaLaunchAttributeProgrammaticStreamSerialization;
    attr[0].val.programmaticStreamSerializationAllowed = 1;

    cudaLaunchConfig_t cfg = {};
    cfg.gridDim = dim3(16, 8);
    cfg.blockDim = dim3(256);
    cfg.dynamicSmemBytes = SMEM_TOTAL;
    cfg.stream = 0;
    cfg.attrs = attr;
    cfg.numAttrs = 1;

    for (int t = 1; t < TT; ++t) {
        cudaLaunchKernelEx(&cfg, mma_step, x, W_ih, b_ih, t, t & 1);
    }
    out_kernel<<<BB / 2, 256>>>(W_ho, b_ho, out);
}

// round 15
// speedup vs baseline: 1.0574x; 1.0574x over previous
#include <cuda_runtime.h>
#include <cuda.h>
#include <cuda_bf16.h>
#include <math.h>
#include <stdint.h>

#define BB 256
#define TT 512
#define HH 1024
#define OO 256

#define CK 64                   // K per chunk PER HALF (chunk covers both halves)
#define NCHUNK 8
#define STAGE_B 49152
#define STAGES 4
#define SMEM_META (STAGES * STAGE_B)          // wx/bi + mbarriers
#define SMEM_TOTAL (STAGES * STAGE_B + 1024)  // 197632

// offsets inside a stage (h = K-half)
#define AH_OFF(h) ((h) * 4096)
#define AL_OFF(h) (8192 + (h) * 4096)
#define BH_OFF(h) (16384 + (h) * 8192)
#define BL_OFF(h) (32768 + (h) * 8192)

__device__ __align__(1024) __nv_bfloat16 g_h_hi[2][BB * HH];
__device__ __align__(1024) __nv_bfloat16 g_h_lo[2][BB * HH];
__device__ __align__(1024) __nv_bfloat16 g_Wt_hi[HH * HH];
__device__ __align__(1024) __nv_bfloat16 g_Wt_lo[HH * HH];

// ---------- PTX helpers (sm_90-generic only; NO tcgen05) ----------
__device__ __forceinline__ uint32_t smem_u32(const void* p) {
    uint32_t a;
    asm("{ .reg .u64 t; cvta.to.shared.u64 t, %1; cvt.u32.u64 %0, t; }" : "=r"(a) : "l"(p));
    return a;
}
#define GRIDDEP_WAIT()   asm volatile("griddepcontrol.wait;" ::: "memory")
#define GRIDDEP_LAUNCH() asm volatile("griddepcontrol.launch_dependents;" ::: "memory")

#define MBAR_INIT(a, n) asm volatile("mbarrier.init.shared.b64 [%0], %1;" :: "r"(a), "r"(n) : "memory")
#define MBAR_EXPECT_TX(a, n) asm volatile("mbarrier.arrive.expect_tx.shared.b64 _, [%0], %1;" :: "r"(a), "r"(n) : "memory")
#define MBAR_WAIT(a, ph) do { \
    uint32_t _m = (a), _p = (ph), _d; \
    asm volatile("{\n\t.reg .pred p;\n\tmbarrier.try_wait.parity.acquire.cta.shared::cta.b64 p, [%1], %2;\n\tselp.b32 %0, 1, 0, p;\n\t}" \
        : "=r"(_d) : "r"(_m), "r"(_p) : "memory"); \
    if (!_d) { \
        asm volatile("{\n\t.reg .pred P1;\n\tWL_%=:\n\tmbarrier.try_wait.parity.acquire.cta.shared::cta.b64 P1, [%0], %1, 0x989680;\n\t@P1 bra.uni WD_%=;\n\tbra.uni WL_%=;\n\tWD_%=:\n\t}" \
            :: "r"(_m), "r"(_p) : "memory"); \
    } } while (0)

__device__ __forceinline__ void tma2d(uint32_t dst, const CUtensorMap* m,
                                      int cx, int cy, uint32_t mbar) {
    asm volatile(
        "cp.async.bulk.tensor.2d.shared::cta.global.tile.mbarrier::complete_tx::bytes "
        "[%0], [%1, {%2, %3}], [%4];"
        :: "r"(dst), "l"(m), "r"(cx), "r"(cy), "r"(mbar) : "memory");
}

__device__ __forceinline__ void ldsm4(uint32_t* r, uint32_t a) {
    asm volatile("ldmatrix.sync.aligned.m8n8.x4.shared.b16 {%0,%1,%2,%3}, [%4];"
                 : "=r"(r[0]), "=r"(r[1]), "=r"(r[2]), "=r"(r[3]) : "r"(a));
}
__device__ __forceinline__ void mma16816(float* c, const uint32_t* a,
                                         uint32_t b0, uint32_t b1) {
    asm volatile(
        "mma.sync.aligned.m16n8k16.row.col.f32.bf16.bf16.f32 "
        "{%0,%1,%2,%3},{%4,%5,%6,%7},{%8,%9},{%0,%1,%2,%3};"
        : "+f"(c[0]), "+f"(c[1]), "+f"(c[2]), "+f"(c[3])
        : "r"(a[0]), "r"(a[1]), "r"(a[2]), "r"(a[3]), "r"(b0), "r"(b1));
}

// Fast tanh: 1 - 2/(e^{2y}+1). Saturates to +/-1; err ~1e-6.
__device__ __forceinline__ float ftanh(float y) {
    float e = __expf(2.f * y);
    return 1.f - __fdividef(2.f, e + 1.f);
}

// ---------- setup kernels ----------

__global__ __launch_bounds__(256) void wsplit_kernel(const float* __restrict__ W_ih) {
    __shared__ float tile[32][33];
    const int k0 = blockIdx.x * 32;
    const int j0 = blockIdx.y * 32;
    const int tx = threadIdx.x & 31;
    const int ty = threadIdx.x >> 5;
    #pragma unroll
    for (int i = 0; i < 4; ++i) {
        int k = ty + i * 8;
        tile[k][tx] = W_ih[(size_t)(1 + k0 + k) * HH + j0 + tx];
    }
    __syncthreads();
    #pragma unroll
    for (int i = 0; i < 4; ++i) {
        int j = ty + i * 8;
        float v = tile[tx][j];
        __nv_bfloat16 hi = __float2bfloat16(v);
        float lo = v - __bfloat162float(hi);
        g_Wt_hi[(size_t)(j0 + j) * HH + k0 + tx] = hi;
        g_Wt_lo[(size_t)(j0 + j) * HH + k0 + tx] = __float2bfloat16(lo);
    }
}

__global__ __launch_bounds__(256) void step0_kernel(
    const float* __restrict__ x, const float* __restrict__ W_ih,
    const float* __restrict__ b_ih) {
    int j = (blockIdx.x & 3) * 256 + threadIdx.x;
    int b = blockIdx.x >> 2;
    float v = tanhf(x[b * TT] * W_ih[j] + b_ih[j]);
    __nv_bfloat16 hi = __float2bfloat16(v);
    g_h_hi[1][b * HH + j] = hi;
    g_h_lo[1][b * HH + j] = __float2bfloat16(v - __bfloat162float(hi));
}

// One step: R12 mainloop with TMA bulk loads + mbarrier pipeline.
// CTA 32(b) x 64(j), 256 threads, 8 warps; warp tile 32x16
// (warp_n = wid&3, kh = wid>>2). SW128 smem (identical layout to R12).
__global__ __launch_bounds__(256, 1) void mma_step(
    const float* __restrict__ x,
    const float* __restrict__ W_ih,
    const float* __restrict__ b_ih,
    int t,
    const __grid_constant__ CUtensorMap tah,
    const __grid_constant__ CUtensorMap tal,
    const __grid_constant__ CUtensorMap tbh,
    const __grid_constant__ CUtensorMap tbl,
    int rd) {
    extern __shared__ __align__(1024) char smem[];
    const uint32_t sb = smem_u32(smem);
    float* wx_s = (float*)(smem + SMEM_META);
    float* bi_s = wx_s + 64;
    const uint32_t mbar = sb + SMEM_META + 512;   // 4 x 8B mbarriers

    const int tid = threadIdx.x;
    const int wid = tid >> 5;
    const int lane = tid & 31;
    const int j0 = blockIdx.x * 64;
    const int m0 = blockIdx.y * 32;

    if (tid < 64) {
        wx_s[tid] = W_ih[j0 + tid];
        bi_s[tid] = b_ih[j0 + tid];
    }
    if (tid == 0) {
        #pragma unroll
        for (int s = 0; s < STAGES; ++s) MBAR_INIT(mbar + s * 8, 1);
    }
    __syncthreads();

#define ISSUE_B(cc, stg) do {                                            \
    const uint32_t st_ = sb + (uint32_t)(stg) * STAGE_B;                 \
    const int k0_ = (cc) * CK;                                           \
    tma2d(st_ + BH_OFF(0), &tbh, k0_,       j0, mbar + (stg) * 8);       \
    tma2d(st_ + BH_OFF(1), &tbh, 512 + k0_, j0, mbar + (stg) * 8);       \
    tma2d(st_ + BL_OFF(0), &tbl, k0_,       j0, mbar + (stg) * 8);       \
    tma2d(st_ + BL_OFF(1), &tbl, 512 + k0_, j0, mbar + (stg) * 8);       \
} while (0)

#define ISSUE_A(cc, stg) do {                                            \
    const uint32_t st_ = sb + (uint32_t)(stg) * STAGE_B;                 \
    const int k0_ = (cc) * CK;                                           \
    tma2d(st_ + AH_OFF(0), &tah, k0_,       m0, mbar + (stg) * 8);       \
    tma2d(st_ + AH_OFF(1), &tah, 512 + k0_, m0, mbar + (stg) * 8);       \
    tma2d(st_ + AL_OFF(0), &tal, k0_,       m0, mbar + (stg) * 8);       \
    tma2d(st_ + AL_OFF(1), &tal, 512 + k0_, m0, mbar + (stg) * 8);       \
} while (0)

    // ---- compute roles (identical to R12) ----
    const int kh = wid >> 2;
    const int warp_n = wid & 3;
    const int lrow = lane & 7;
    const uint32_t arow0 = (uint32_t)(lrow + ((lane >> 3) & 1) * 8) * 128;
    const uint32_t arow1 = arow0 + 16 * 128;
    const uint32_t brow  = (uint32_t)(warp_n * 16 + lrow + (lane >> 4) * 8) * 128;
    const int acsel = lane >> 4;
    const int bcsel = (lane >> 3) & 1;
    const uint32_t ahb = AH_OFF(kh), alb = AL_OFF(kh);
    const uint32_t bhb = BH_OFF(kh), blb = BL_OFF(kh);

#define LOAD_FRAGS(i_, stb_, kk_) do {                                   \
    const uint32_t cA = (uint32_t)((2 * (kk_) + acsel) ^ lrow) * 16;     \
    const uint32_t cB = (uint32_t)((2 * (kk_) + bcsel) ^ lrow) * 16;     \
    ldsm4(&ah[i_][0][0], (stb_) + ahb + arow0 + cA);                     \
    ldsm4(&ah[i_][1][0], (stb_) + ahb + arow1 + cA);                     \
    ldsm4(&al[i_][0][0], (stb_) + alb + arow0 + cA);                     \
    ldsm4(&al[i_][1][0], (stb_) + alb + arow1 + cA);                     \
    ldsm4(bh[i_], (stb_) + bhb + brow + cB);                             \
    ldsm4(bl[i_], (stb_) + blb + brow + cB);                             \
} while (0)

    // x prefetch: the 2 rows this warp finalizes (m-block = kh)
    const int er0 = m0 + kh * 16 + (lane >> 2);
    float xv0 = x[er0 * TT + t];
    float xv1 = x[(er0 + 8) * TT + t];

    // ---- PDL prologue: arm + W for stages 0-3 pre-wait, A after ----
    if (tid == 0) {
        #pragma unroll
        for (int s = 0; s < STAGES; ++s) {
            MBAR_EXPECT_TX(mbar + s * 8, STAGE_B);
            ISSUE_B(s, s);
        }
    }
    GRIDDEP_WAIT();   // previous step's h now visible
    if (tid == 0) {
        #pragma unroll
        for (int s = 0; s < STAGES; ++s) ISSUE_A(s, s);
    }

    float acc[2][3][2][4];
    #pragma unroll
    for (int m = 0; m < 2; ++m)
        #pragma unroll
        for (int p = 0; p < 3; ++p)
            #pragma unroll
            for (int n = 0; n < 2; ++n)
                #pragma unroll
                for (int i = 0; i < 4; ++i) acc[m][p][n][i] = 0.f;

    #pragma unroll 1
    for (int c = 0; c < NCHUNK; ++c) {
        MBAR_WAIT(mbar + (c & 3) * 8, (c >> 2) & 1);

        const uint32_t stb = sb + (uint32_t)(c & 3) * STAGE_B;
        uint32_t ah[2][2][4], al[2][2][4], bh[2][4], bl[2][4];
        LOAD_FRAGS(0, stb, 0);
        #pragma unroll
        for (int kk = 0; kk < CK / 16; ++kk) {
            const int cur = kk & 1;
            if (kk < CK / 16 - 1) LOAD_FRAGS(cur ^ 1, stb, kk + 1);
            #pragma unroll
            for (int m = 0; m < 2; ++m) {
                mma16816(acc[m][0][0], ah[cur][m], bh[cur][0], bh[cur][1]);
                mma16816(acc[m][0][1], ah[cur][m], bh[cur][2], bh[cur][3]);
                mma16816(acc[m][1][0], ah[cur][m], bl[cur][0], bl[cur][1]);
                mma16816(acc[m][1][1], ah[cur][m], bl[cur][2], bl[cur][3]);
                mma16816(acc[m][2][0], al[cur][m], bh[cur][0], bh[cur][1]);
                mma16816(acc[m][2][1], al[cur][m], bh[cur][2], bh[cur][3]);
            }
        }

        __syncthreads();   // all warps done reading stage c&3
        if (tid == 0 && c + 4 < NCHUNK) {
            MBAR_EXPECT_TX(mbar + (c & 3) * 8, STAGE_B);
            ISSUE_B(c + 4, c & 3);
            ISSUE_A(c + 4, c & 3);
        }
    }

    GRIDDEP_LAUNCH();  // next step may launch during our tail

    float s[2][2][4];
    #pragma unroll
    for (int m = 0; m < 2; ++m)
        #pragma unroll
        for (int n = 0; n < 2; ++n)
            #pragma unroll
            for (int i = 0; i < 4; ++i)
                s[m][n][i] = acc[m][0][n][i] + acc[m][1][n][i] + acc[m][2][n][i];

    // ---- symmetric cross-half exchange: warp finalizes m-block == kh ----
    float* scratch = (float*)smem;   // stage 0 region, free after last sync
    const uint32_t slot = (uint32_t)(warp_n * 32 + lane) * 8;
    const int om = kh ^ 1;
    {
        float4* p = (float4*)(scratch + (uint32_t)kh * 1024 + slot);
        p[0] = make_float4(s[om][0][0], s[om][0][1], s[om][0][2], s[om][0][3]);
        p[1] = make_float4(s[om][1][0], s[om][1][1], s[om][1][2], s[om][1][3]);
    }
    __syncthreads();
    {
        const float4* q = (const float4*)(scratch + (uint32_t)om * 1024 + slot);
        float4 q0 = q[0], q1 = q[1];
        s[kh][0][0] += q0.x; s[kh][0][1] += q0.y; s[kh][0][2] += q0.z; s[kh][0][3] += q0.w;
        s[kh][1][0] += q1.x; s[kh][1][1] += q1.y; s[kh][1][2] += q1.z; s[kh][1][3] += q1.w;
    }

    // ---- epilogue: every warp writes its own 16-row m-block ----
    {
        __nv_bfloat16* ph = g_h_hi[rd ^ 1];
        __nv_bfloat16* pl = g_h_lo[rd ^ 1];
        const int r0 = er0;
        const int r1 = r0 + 8;
        #pragma unroll
        for (int n = 0; n < 2; ++n) {
            const int cj = warp_n * 16 + n * 8 + (lane & 3) * 2;
            const float wxa = wx_s[cj], wxb = wx_s[cj + 1];
            const float bia = bi_s[cj], bib = bi_s[cj + 1];
            float v00 = ftanh(s[kh][n][0] + xv0 * wxa + bia);
            float v01 = ftanh(s[kh][n][1] + xv0 * wxb + bib);
            float v10 = ftanh(s[kh][n][2] + xv1 * wxa + bia);
            float v11 = ftanh(s[kh][n][3] + xv1 * wxb + bib);

            __nv_bfloat162 h0, l0, h1, l1;
            h0.x = __float2bfloat16(v00); h0.y = __float2bfloat16(v01);
            l0.x = __float2bfloat16(v00 - __bfloat162float(h0.x));
            l0.y = __float2bfloat16(v01 - __bfloat162float(h0.y));
            h1.x = __float2bfloat16(v10); h1.y = __float2bfloat16(v11);
            l1.x = __float2bfloat16(v10 - __bfloat162float(h1.x));
            l1.y = __float2bfloat16(v11 - __bfloat162float(h1.y));

            const size_t o0 = (size_t)r0 * HH + j0 + cj;
            const size_t o1 = (size_t)r1 * HH + j0 + cj;
            *(uint32_t*)(ph + o0) = *(uint32_t*)&h0;
            *(uint32_t*)(pl + o0) = *(uint32_t*)&l0;
            *(uint32_t*)(ph + o1) = *(uint32_t*)&h1;
            *(uint32_t*)(pl + o1) = *(uint32_t*)&l1;
        }
    }
#undef ISSUE_B
#undef ISSUE_A
#undef LOAD_FRAGS
}

// out = h_final @ W_ho + b_ho ; h_final = hi+lo in buffer 0
__global__ __launch_bounds__(256) void out_kernel(
    const float* __restrict__ W_ho, const float* __restrict__ b_ho,
    float* __restrict__ out) {
    __shared__ __align__(16) float hsm[2 * HH];
    const int b0 = blockIdx.x * 2;
    const __nv_bfloat16* sh = &g_h_hi[0][(size_t)b0 * HH];
    const __nv_bfloat16* sl = &g_h_lo[0][(size_t)b0 * HH];
    for (int i = threadIdx.x; i < 2 * HH; i += 256)
        hsm[i] = __bfloat162float(sh[i]) + __bfloat162float(sl[i]);
    __syncthreads();

    const int o = threadIdx.x;
    float a0 = 0.f, a1 = 0.f;
    #pragma unroll 16
    for (int k = 0; k < HH; ++k) {
        float w = W_ho[k * OO + o];
        a0 += hsm[k] * w;
        a1 += hsm[HH + k] * w;
    }
    out[b0 * OO + o]       = a0 + b_ho[o];
    out[(b0 + 1) * OO + o] = a1 + b_ho[o];
}

// ---------- host ----------
typedef CUresult (*PFN_encode)(
    CUtensorMap*, CUtensorMapDataType, cuuint32_t, void*,
    const cuuint64_t*, const cuuint64_t*, const cuuint32_t*, const cuuint32_t*,
    CUtensorMapInterleave, CUtensorMapSwizzle, CUtensorMapL2promotion,
    CUtensorMapFloatOOBfill);

static void make_desc(PFN_encode enc, CUtensorMap* m, void* base,
                      uint64_t d0, uint64_t d1, uint32_t b0, uint32_t b1) {
    cuuint64_t dims[2] = {d0, d1};
    cuuint64_t strides[1] = {d0 * 2};
    cuuint32_t box[2] = {b0, b1};
    cuuint32_t es[2] = {1, 1};
    enc(m, CU_TENSOR_MAP_DATA_TYPE_BFLOAT16, 2, base, dims, strides, box, es,
        CU_TENSOR_MAP_INTERLEAVE_NONE, CU_TENSOR_MAP_SWIZZLE_128B,
        CU_TENSOR_MAP_L2_PROMOTION_L2_128B, CU_TENSOR_MAP_FLOAT_OOB_FILL_NONE);
}

extern "C" void kernel_launch(void* const* d_in, const int* in_sizes, int n_in,
                              void* d_out, int out_size) {
    const float* x    = (const float*)d_in[0];
    const float* W_ih = (const float*)d_in[1];
    const float* b_ih = (const float*)d_in[2];
    const float* W_ho = (const float*)d_in[3];
    const float* b_ho = (const float*)d_in[4];
    float* out = (float*)d_out;

    static int once = 0;
    static CUtensorMap ah[2], al[2], bh, bl;
    if (!once) {
        cudaFuncSetAttribute(mma_step, cudaFuncAttributeMaxDynamicSharedMemorySize,
                             SMEM_TOTAL);
        PFN_encode enc = nullptr;
        cudaDriverEntryPointQueryResult qr;
        cudaGetDriverEntryPoint("cuTensorMapEncodeTiled", (void**)&enc,
                                cudaEnableDefault, &qr);
        void *p_hhi, *p_hlo, *p_wth, *p_wtl;
        cudaGetSymbolAddress(&p_hhi, g_h_hi);
        cudaGetSymbolAddress(&p_hlo, g_h_lo);
        cudaGetSymbolAddress(&p_wth, g_Wt_hi);
        cudaGetSymbolAddress(&p_wtl, g_Wt_lo);
        for (int i = 0; i < 2; ++i) {
            make_desc(enc, &ah[i], (char*)p_hhi + (size_t)i * BB * HH * 2, HH, BB, CK, 32);
            make_desc(enc, &al[i], (char*)p_hlo + (size_t)i * BB * HH * 2, HH, BB, CK, 32);
        }
        make_desc(enc, &bh, p_wth, HH, HH, CK, 64);
        make_desc(enc, &bl, p_wtl, HH, HH, CK, 64);
        once = 1;
    }

    wsplit_kernel<<<dim3(32, 32), 256>>>(W_ih);
    step0_kernel<<<BB * 4, 256>>>(x, W_ih, b_ih);

    cudaLaunchAttribute attr[1];
    attr[0].id = cudaLaunchAttributeProgrammaticStreamSerialization;
    attr[0].val.programmaticStreamSerializationAllowed = 1;

    cudaLaunchConfig_t cfg = {};
    cfg.gridDim = dim3(16, 8);
    cfg.blockDim = dim3(256);
    cfg.dynamicSmemBytes = SMEM_TOTAL;
    cfg.stream = 0;
    cfg.attrs = attr;
    cfg.numAttrs = 1;

    for (int t = 1; t < TT; ++t) {
        const int rd = t & 1;
        cudaLaunchKernelEx(&cfg, mma_step, x, W_ih, b_ih, t,
                           ah[rd], al[rd], bh, bl, rd);
    }
    out_kernel<<<BB / 2, 256>>>(W_ho, b_ho, out);
}